// round 3
// baseline (speedup 1.0000x reference)
#include <cuda_runtime.h>
#include <cstdint>

#define B 64
#define K 8
#define V 128000
#define NCH 64
#define CH 2000           // V / NCH
#define PLACEHOLDER_F (-1.0f)

// scratch (no allocations allowed)
__device__ float g_csum[B * NCH];
__device__ float g_cmax[B * NCH];
__device__ int   g_camax[B * NCH];
__device__ int   g_j[B];
__device__ int   g_na[B];

// ---------------------------------------------------------------------------
// Kernel 1: accept/reject, num_accepted, j, all output fields except recovered
// ---------------------------------------------------------------------------
__global__ void k1_accept(const int* __restrict__ dtok,
                          const float* __restrict__ dp,
                          const float* __restrict__ tp,
                          const int* __restrict__ bonus,
                          const float* __restrict__ us,
                          float* __restrict__ out) {
    __shared__ int acc[B * K];
    int tid = threadIdx.x;               // 512 threads = B*K
    int tok = dtok[tid];
    size_t off = (size_t)tid * V + (size_t)tok;
    float p = tp[off];
    float q = dp[off];
    float ap = fminf(1.0f, p / fmaxf(q, 1e-10f));
    acc[tid] = (us[tid] < ap) ? 1 : 0;
    __syncthreads();
    if (tid < B) {
        int b = tid;
        int na = 0;
        for (int i = 0; i < K; i++) {
            if (acc[b * K + i]) na++; else break;
        }
        g_na[b] = na;
        g_j[b] = (na < K) ? na : (K - 1);
        bool all = (na == K);
        for (int pos = 0; pos <= K; pos++) {
            float v;
            if (pos < na)        v = (float)dtok[b * K + pos];
            else if (pos == na)  v = all ? (float)bonus[b] : PLACEHOLDER_F; // k3 fills recovered
            else                 v = PLACEHOLDER_F;
            out[b * (K + 1) + pos] = v;
        }
        int base = B * (K + 1);
        out[base + b]         = (float)na;          // num_accepted
        out[base + B + b]     = (float)na;          // accepted_counts
        out[base + 2 * B + b] = all ? 0.0f : 1.0f;  // recovered_counts
        out[base + 3 * B + b] = all ? 1.0f : 0.0f;  // bonus_counts
    }
}

// ---------------------------------------------------------------------------
// Kernel 2: per-(b,chunk) residual sum + chunk max/argmax of target row
// ---------------------------------------------------------------------------
__global__ void k2_chunks(const float* __restrict__ dp,
                          const float* __restrict__ tp) {
    int c = blockIdx.x;          // chunk 0..63
    int b = blockIdx.y;          // batch 0..63
    int t = threadIdx.x;         // 256
    int j = g_j[b];
    size_t base = ((size_t)(b * K + j)) * V + (size_t)c * CH;
    const float4* t4 = (const float4*)(tp + base);
    const float4* d4 = (const float4*)(dp + base);

    float s = 0.0f;
    float mx = -1.0f;
    int   mi = V;
    const int N4 = CH / 4;       // 500
    for (int i = t; i < N4; i += 256) {
        float4 tv = t4[i];
        float4 dv = d4[i];
        s += fmaxf(tv.x - dv.x, 0.0f);
        s += fmaxf(tv.y - dv.y, 0.0f);
        s += fmaxf(tv.z - dv.z, 0.0f);
        s += fmaxf(tv.w - dv.w, 0.0f);
        int gi = c * CH + i * 4;
        // strict > keeps first occurrence within the (increasing) thread walk
        if (tv.x > mx) { mx = tv.x; mi = gi; }
        if (tv.y > mx) { mx = tv.y; mi = gi + 1; }
        if (tv.z > mx) { mx = tv.z; mi = gi + 2; }
        if (tv.w > mx) { mx = tv.w; mi = gi + 3; }
    }

    __shared__ float ssum[256];
    __shared__ float smax[256];
    __shared__ int   sidx[256];
    ssum[t] = s; smax[t] = mx; sidx[t] = mi;
    __syncthreads();
    for (int st = 128; st > 0; st >>= 1) {
        if (t < st) {
            ssum[t] += ssum[t + st];
            float ov = smax[t + st]; int oi = sidx[t + st];
            if (ov > smax[t] || (ov == smax[t] && oi < sidx[t])) {
                smax[t] = ov; sidx[t] = oi;
            }
        }
        __syncthreads();
    }
    if (t == 0) {
        g_csum[b * NCH + c]  = ssum[0];
        g_cmax[b * NCH + c]  = smax[0];
        g_camax[b * NCH + c] = sidx[0];
    }
}

// ---------------------------------------------------------------------------
// Kernel 3: locate the sampled index inside the crossing chunk
// ---------------------------------------------------------------------------
__global__ void k3_finalize(const float* __restrict__ dp,
                            const float* __restrict__ tp,
                            const float* __restrict__ us,
                            float* __restrict__ out) {
    int b = blockIdx.x;
    int t = threadIdx.x;   // 256

    __shared__ float cum[NCH];
    __shared__ float thr_s, pref_s, total_s;
    __shared__ int   cidx, fb_amax, cand;
    __shared__ float segsum[256];
    __shared__ float segex[256];

    int na = g_na[b];
    int j  = g_j[b];

    if (t == 0) {
        float run = 0.0f;
        for (int c = 0; c < NCH; c++) { run += g_csum[b * NCH + c]; cum[c] = run; }
        total_s = run;
        float thr = us[b * K + j] * run;
        thr_s = thr;
        int c = NCH - 1;
        for (int i = 0; i < NCH; i++) if (cum[i] > thr) { c = i; break; }
        cidx = c;
        pref_s = (c > 0) ? cum[c - 1] : 0.0f;
        // fallback argmax(target row), first occurrence
        float mx = -1.0f; int mi = V;
        for (int ci = 0; ci < NCH; ci++) {
            float v = g_cmax[b * NCH + ci];
            int id  = g_camax[b * NCH + ci];
            if (v > mx || (v == mx && id < mi)) { mx = v; mi = id; }
        }
        fb_amax = mi;
        cand = V - 1;   // safety default (measure-zero boundary rounding)
    }
    __syncthreads();

    int c = cidx;
    size_t base = ((size_t)(b * K + j)) * V + (size_t)c * CH;

    // 250 contiguous 8-elem segments cover CH=2000
    float rv[8];
    float ls = 0.0f;
    int s0 = t * 8;
    if (s0 < CH) {
        #pragma unroll
        for (int e = 0; e < 8; e++) {
            int ii = s0 + e;
            float r = (ii < CH) ? fmaxf(tp[base + ii] - dp[base + ii], 0.0f) : 0.0f;
            rv[e] = r; ls += r;
        }
    }
    segsum[t] = (s0 < CH) ? ls : 0.0f;
    __syncthreads();
    if (t == 0) {
        float run = pref_s;
        for (int i = 0; i < 256; i++) { segex[i] = run; run += segsum[i]; }
    }
    __syncthreads();

    if (s0 < CH) {
        float run = segex[t];
        float thr = thr_s;
        #pragma unroll
        for (int e = 0; e < 8; e++) {
            int ii = s0 + e;
            if (ii >= CH) break;
            run += rv[e];
            if (run > thr) { atomicMin(&cand, c * CH + ii); break; }
        }
    }
    __syncthreads();

    if (t == 0) {
        int rec = (total_s > 0.0f) ? cand : fb_amax;
        if (na < K) out[b * (K + 1) + na] = (float)rec;
    }
}

// ---------------------------------------------------------------------------
extern "C" void kernel_launch(void* const* d_in, const int* in_sizes, int n_in,
                              void* d_out, int out_size) {
    const int*   dtok  = (const int*)d_in[0];   // [B,K]
    const float* dp    = (const float*)d_in[1]; // [B,K,V] draft probs
    const float* tp    = (const float*)d_in[2]; // [B,K,V] target probs
    const int*   bonus = (const int*)d_in[3];   // [B]
    const float* us    = (const float*)d_in[4]; // [B,K]
    float* out = (float*)d_out;

    k1_accept<<<1, B * K>>>(dtok, dp, tp, bonus, us, out);
    dim3 g2(NCH, B);
    k2_chunks<<<g2, 256>>>(dp, tp);
    k3_finalize<<<B, 256>>>(dp, tp, us, out);
}